// round 6
// baseline (speedup 1.0000x reference)
#include <cuda_runtime.h>
#include <cuda_bf16.h>
#include <math.h>
#include <cstdint>

#define N_NODES 100000
#define F_DIM   128
#define DEG     5
#define N_EDGES (N_NODES * DEG)
#define MIN_NORM 1e-15f
#define MAXNORM  0.996f

// ---------------- scratch ----------------------------------------------------
__device__ __align__(16) float g_mxT[(size_t)N_NODES * F_DIM];
__device__ __align__(16) float g_u[N_NODES];
__device__ __align__(16) float g_v[N_NODES];
__device__ int   g_cnt[N_NODES];
__device__ __align__(16) float g_msq[F_DIM];
__device__ __align__(16) float g_wsq[F_DIM];
__device__ __align__(16) float g_xs2[F_DIM];
__device__ __align__(16) float g_alpha[F_DIM];
__device__ __align__(16) float g_c1[F_DIM];
__device__ __align__(16) float g_c2[F_DIM];
__device__ float g_sumsqE;
__device__ float g_anorm;

// ---------------- math helpers ------------------------------------------------
__device__ __forceinline__ float clip1(float x) {
    return fminf(fmaxf(x, -1.0f + 1e-7f), 1.0f - 1e-7f);
}
__device__ __forceinline__ float artanh_c(float x) { return atanhf(clip1(x)); }
__device__ __forceinline__ float proj_logmap0_factor(float s, float mn) {
    float r  = fabsf(s) * mn;
    float pf = (r > MAXNORM) ? (MAXNORM / r) : 1.0f;
    float pn = fmaxf(r * pf, MIN_NORM);
    return s * pf * artanh_c(pn) / pn;
}
__device__ __forceinline__ float expmap0_proj_factor(float un) {
    un = fmaxf(un, MIN_NORM);
    float g  = tanhf(un) / un;
    float r  = fabsf(g) * un;
    float pf = (r > MAXNORM) ? (MAXNORM / r) : 1.0f;
    return g * pf;
}

__device__ __forceinline__ uint32_t smem_u32(const void* p) {
    uint32_t a;
    asm("{ .reg .u64 t; cvta.to.shared.u64 t, %1; cvt.u32.u64 %0, t; }" : "=r"(a) : "l"(p));
    return a;
}

#define CVTPK(r, f0, f1) asm("cvt.rn.bf16x2.f32 %0, %1, %2;" : "=r"(r) : "f"(f1), "f"(f0))

#define LDSM_X4(r0, r1, r2, r3, addr)                                            \
    asm volatile("ldmatrix.sync.aligned.m8n8.x4.shared.b16 {%0,%1,%2,%3}, [%4];" \
        : "=r"(r0), "=r"(r1), "=r"(r2), "=r"(r3) : "r"(addr))

#define MMA_BF16(cp, a0, a1, a2, a3, b0, b1)                                     \
    asm volatile("mma.sync.aligned.m16n8k16.row.col.f32.bf16.bf16.f32 "          \
        "{%0,%1,%2,%3}, {%4,%5,%6,%7}, {%8,%9}, {%0,%1,%2,%3};"                  \
        : "+f"((cp)[0]), "+f"((cp)[1]), "+f"((cp)[2]), "+f"((cp)[3])             \
        : "r"(a0), "r"(a1), "r"(a2), "r"(a3), "r"(b0), "r"(b1))

// ---------------- K0: zero + W row norms (merged) ------------------------------
__global__ void k_zw(const float* __restrict__ W) {
    int i = blockIdx.x * 256 + threadIdx.x;
    if (i < N_NODES) g_cnt[i] = 0;
    if (i < F_DIM) { g_msq[i] = 0.0f; g_wsq[i] = 0.0f; }
    if (i == 0) g_sumsqE = 0.0f;
    if (blockIdx.x < 16) {
        int w    = blockIdx.x * 8 + (threadIdx.x >> 5);
        int lane = threadIdx.x & 31;
        float4 v = *(const float4*)&W[w * 128 + lane * 4];
        float s = v.x * v.x + v.y * v.y + v.z * v.z + v.w * v.w;
#pragma unroll
        for (int o = 16; o > 0; o >>= 1) s += __shfl_xor_sync(0xffffffffu, s, o);
        if (lane == 0) g_xs2[w] = s;
    }
}
__global__ void k_hist(const int* __restrict__ dst) {
    int e = blockIdx.x * blockDim.x + threadIdx.x;
    if (e < N_EDGES) atomicAdd(&g_cnt[dst[e]], 1);
}

// ---------------- K1: mma.sync bf16 3-split GEMM, K-chunked, m32n64 warps ------
// Block: 256 thr (8 warps), tile M=128 N=128, K in 2 chunks of 64.
// smem per chunk: A[128][72]bf16 hi/lo + B[128][72]bf16 hi/lo = 72 KB.
#define ROWB   144                       // 72 bf16 per row
#define ATILEB (128 * ROWB)              // 18432
#define SM_AH  0
#define SM_AL  (SM_AH + ATILEB)
#define SM_BH  (SM_AL + ATILEB)
#define SM_BL  (SM_BH + ATILEB)
#define SM_TOT (SM_BL + ATILEB)          // 73728

__device__ __forceinline__ void conv8(char* smem, uint32_t hi_base, uint32_t lo_base,
                                      uint32_t off, float4 a, float4 b) {
    uint32_t p0, p1, p2, p3, q0, q1, q2, q3;
    CVTPK(p0, a.x, a.y); CVTPK(p1, a.z, a.w);
    CVTPK(p2, b.x, b.y); CVTPK(p3, b.z, b.w);
    float l0 = a.x - __uint_as_float(p0 << 16);
    float l1 = a.y - __uint_as_float(p0 & 0xffff0000u);
    float l2 = a.z - __uint_as_float(p1 << 16);
    float l3 = a.w - __uint_as_float(p1 & 0xffff0000u);
    float l4 = b.x - __uint_as_float(p2 << 16);
    float l5 = b.y - __uint_as_float(p2 & 0xffff0000u);
    float l6 = b.z - __uint_as_float(p3 << 16);
    float l7 = b.w - __uint_as_float(p3 & 0xffff0000u);
    CVTPK(q0, l0, l1); CVTPK(q1, l2, l3); CVTPK(q2, l4, l5); CVTPK(q3, l6, l7);
    *(uint4*)(smem + hi_base + off) = make_uint4(p0, p1, p2, p3);
    *(uint4*)(smem + lo_base + off) = make_uint4(q0, q1, q2, q3);
}

// one split pass over a 64-wide K chunk: warp tile m32 x n64
__device__ __forceinline__ void mma_pass(uint32_t a_base, uint32_t b_base, float c[2][8][4]) {
#pragma unroll
    for (int ks = 0; ks < 4; ks++) {
        uint32_t a0, a1, a2, a3, a4, a5, a6, a7;
        LDSM_X4(a0, a1, a2, a3, a_base + ks * 32);
        LDSM_X4(a4, a5, a6, a7, a_base + 16 * ROWB + ks * 32);
#pragma unroll
        for (int jj = 0; jj < 4; jj++) {
            uint32_t b0, b1, b2, b3;
            LDSM_X4(b0, b1, b2, b3, b_base + jj * (16 * ROWB) + ks * 32);
            MMA_BF16(c[0][2 * jj],     a0, a1, a2, a3, b0, b1);
            MMA_BF16(c[0][2 * jj + 1], a0, a1, a2, a3, b2, b3);
            MMA_BF16(c[1][2 * jj],     a4, a5, a6, a7, b0, b1);
            MMA_BF16(c[1][2 * jj + 1], a4, a5, a6, a7, b2, b3);
        }
    }
}

__global__ __launch_bounds__(256, 2) void k_gemm_mma(const float* __restrict__ x,
                                                     const float* __restrict__ W) {
    extern __shared__ __align__(1024) char smem[];
    const uint32_t sbase = smem_u32(smem);
    const int tid  = threadIdx.x;
    const int wid  = tid >> 5;
    const int lane = tid & 31;
    const int base = blockIdx.x * 128;

    const int wm = wid & 3, wn = wid >> 2;
    const int wbase = wm * 32, nbase = wn * 64;

    const uint32_t a_off = (uint32_t)(wbase + (lane & 15)) * ROWB + ((lane >> 4) ? 16u : 0u);
    const uint32_t b_row = (uint32_t)(nbase + ((lane >> 4) << 3) + (lane & 7));
    const uint32_t b_off = b_row * ROWB + (((lane >> 3) & 1) ? 16u : 0u);

    float c[2][8][4];
#pragma unroll
    for (int m = 0; m < 2; m++)
#pragma unroll
        for (int i = 0; i < 8; i++)
#pragma unroll
            for (int j = 0; j < 4; j++) c[m][i][j] = 0.0f;

#pragma unroll
    for (int chunk = 0; chunk < 2; chunk++) {
        const int kc = chunk * 64;
        __syncthreads();
        // stage + split-convert A (x rows) for this K chunk: 128 rows x 8 groups
#pragma unroll
        for (int it = 0; it < 4; it++) {
            int i = tid + it * 256;
            int row = i >> 3, g = i & 7;
            int grow = base + row;
            float4 a = make_float4(0.f, 0.f, 0.f, 0.f), b = a;
            if (grow < N_NODES) {
                const float* p = &x[(size_t)grow * 128 + kc + g * 8];
                a = *(const float4*)p;
                b = *(const float4*)(p + 4);
            }
            conv8(smem, SM_AH, SM_AL, (uint32_t)row * ROWB + g * 16, a, b);
        }
        // stage + split-convert B (W rows) for this K chunk: 128 rows x 8 groups
#pragma unroll
        for (int it = 0; it < 4; it++) {
            int i = tid + it * 256;
            int row = i >> 3, g = i & 7;
            const float* p = &W[row * 128 + kc + g * 8];
            float4 a = *(const float4*)p;
            float4 b = *(const float4*)(p + 4);
            conv8(smem, SM_BH, SM_BL, (uint32_t)row * ROWB + g * 16, a, b);
        }
        __syncthreads();

        mma_pass(sbase + SM_AH + a_off, sbase + SM_BH + b_off, c);   // hi*hi
        mma_pass(sbase + SM_AH + a_off, sbase + SM_BL + b_off, c);   // hi*lo
        mma_pass(sbase + SM_AL + a_off, sbase + SM_BH + b_off, c);   // lo*hi
    }

    // --- epilogue: store mxT + per-feature column sums ---------------------------
    int r0 = base + wbase + (lane >> 2);
    int rows[4] = {r0, r0 + 8, r0 + 16, r0 + 24};
    float cf[4];
    bool vv[4];
#pragma unroll
    for (int i = 0; i < 4; i++) {
        vv[i] = rows[i] < N_NODES;
        cf[i] = vv[i] ? (float)g_cnt[rows[i]] : 0.0f;
    }

    __syncthreads();                       // tiles no longer read; reuse for red
    float* red = (float*)smem;             // [8 warps][128]
    float* redw = red + wid * 128;

#pragma unroll
    for (int nt = 0; nt < 8; nt++) {
        int col = nbase + nt * 8 + (lane & 3) * 2;
        float va[8] = {c[0][nt][0], c[0][nt][1], c[0][nt][2], c[0][nt][3],
                       c[1][nt][0], c[1][nt][1], c[1][nt][2], c[1][nt][3]};
        if (vv[0]) *(float2*)&g_mxT[(size_t)rows[0] * 128 + col] = make_float2(va[0], va[1]);
        if (vv[1]) *(float2*)&g_mxT[(size_t)rows[1] * 128 + col] = make_float2(va[2], va[3]);
        if (vv[2]) *(float2*)&g_mxT[(size_t)rows[2] * 128 + col] = make_float2(va[4], va[5]);
        if (vv[3]) *(float2*)&g_mxT[(size_t)rows[3] * 128 + col] = make_float2(va[6], va[7]);
        float s0 = 0.f, s1 = 0.f, w0 = 0.f, w1 = 0.f;
#pragma unroll
        for (int i = 0; i < 4; i++) {
            float q0 = va[2 * i] * va[2 * i], q1 = va[2 * i + 1] * va[2 * i + 1];
            s0 += q0; s1 += q1;
            w0 += cf[i] * q0; w1 += cf[i] * q1;
        }
#pragma unroll
        for (int o = 4; o <= 16; o <<= 1) {
            s0 += __shfl_xor_sync(0xffffffffu, s0, o);
            s1 += __shfl_xor_sync(0xffffffffu, s1, o);
            w0 += __shfl_xor_sync(0xffffffffu, w0, o);
            w1 += __shfl_xor_sync(0xffffffffu, w1, o);
        }
        if (lane < 4) {
            int lc = nt * 8 + lane * 2;
            redw[lc]          = s0;
            redw[lc + 1]      = s1;
            redw[64 + lc]     = w0;
            redw[64 + lc + 1] = w1;
        }
    }
    __syncthreads();

    // cross-warp reduce: 4 m-warps contribute to each column half
    {
        int col = tid & 127, arr = tid >> 7;    // 256 threads: arr 0=msq, 1=wsq
        int wnc = col >> 6, lc = (col & 63) + arr * 64;
        float s = 0.0f;
#pragma unroll
        for (int wmc = 0; wmc < 4; wmc++) s += red[(wnc * 4 + wmc) * 128 + lc];
        atomicAdd(arr ? &g_wsq[col] : &g_msq[col], s);
    }
}

// ---------------- K2: per-feature scalar chain --------------------------------
__global__ __launch_bounds__(256) void k_scalars(const float* __restrict__ a) {
    __shared__ float sred[256];
    int tid = threadIdx.x;
    float av = a[tid];
    sred[tid] = av * av;
    __syncthreads();
    for (int s = 128; s > 0; s >>= 1) {
        if (tid < s) sred[tid] += sred[tid + s];
        __syncthreads();
    }
    float an = fmaxf(sqrtf(sred[0]), MIN_NORM);
    if (tid == 0) g_anorm = an;

    if (tid < 128) {
        int f = tid;
        float xn = fmaxf(sqrtf(g_xs2[f]), MIN_NORM);
        float mn = fmaxf(sqrtf(g_msq[f]), MIN_NORM);
        float s1 = tanhf(mn / xn * artanh_c(xn)) / mn;
        float alpha = proj_logmap0_factor(s1, mn);
        g_alpha[f] = alpha;
        float un_s = fabsf(alpha) * sqrtf(5.0f * g_msq[f]);
        float un_d = fabsf(alpha) * sqrtf(g_wsq[f]);
        g_c1[f] = a[f]       * expmap0_proj_factor(un_s) * alpha;
        g_c2[f] = a[128 + f] * expmap0_proj_factor(un_d) * alpha;
    }
}

// ---------------- K3: per-node dots -------------------------------------------
__global__ void k_uv() {
    int gw   = (blockIdx.x * blockDim.x + threadIdx.x) >> 5;
    int lane = threadIdx.x & 31;
    if (gw >= N_NODES) return;
    float4 c1 = *(const float4*)&g_c1[lane * 4];
    float4 c2 = *(const float4*)&g_c2[lane * 4];
    float4 m  = *(const float4*)&g_mxT[(size_t)gw * 128 + lane * 4];
    float du = m.x * c1.x + m.y * c1.y + m.z * c1.z + m.w * c1.w;
    float dv = m.x * c2.x + m.y * c2.y + m.z * c2.z + m.w * c2.w;
#pragma unroll
    for (int o = 16; o > 0; o >>= 1) {
        du += __shfl_xor_sync(0xffffffffu, du, o);
        dv += __shfl_xor_sync(0xffffffffu, dv, o);
    }
    if (lane == 0) { g_u[gw] = du; g_v[gw] = dv; }
}

// ---------------- K4: sum of squares of edge logits ---------------------------
__global__ void k_sumsq(const int* __restrict__ src, const int* __restrict__ dst) {
    __shared__ float sb[256];
    int e = blockIdx.x * blockDim.x + threadIdx.x;
    float sq = 0.0f;
    if (e < N_EDGES) {
        float m = g_u[src[e]] + g_v[dst[e]];
        sq = m * m;
    }
    sb[threadIdx.x] = sq;
    __syncthreads();
    for (int s = 128; s > 0; s >>= 1) {
        if (threadIdx.x < s) sb[threadIdx.x] += sb[threadIdx.x + s];
        __syncthreads();
    }
    if (threadIdx.x == 0) atomicAdd(&g_sumsqE, sb[0]);
}

// ---------------- K5: final aggregation ----------------------------------------
__device__ __forceinline__ float compute_gamma() {
    float mn = fmaxf(sqrtf(g_sumsqE), MIN_NORM);
    float an = g_anorm;
    float s2 = tanhf(mn / an * artanh_c(an)) / mn;
    return proj_logmap0_factor(s2, mn);
}

__global__ __launch_bounds__(256) void k_final(const int* __restrict__ src,
                                               const int* __restrict__ dst,
                                               float* __restrict__ out) {
    int n    = (blockIdx.x * blockDim.x + threadIdx.x) >> 5;
    int lane = threadIdx.x & 31;
    if (n >= N_NODES) return;
    float gamma = compute_gamma();

    float wj = 0.0f;
    int   dj = 0;
    if (lane < DEG) {
        int e = n * DEG + lane;
        int s = src[e];
        dj = dst[e];
        float mxE = g_u[s] + g_v[dj];
        float ee  = gamma * mxE;
        float ge  = 0.5f * ee * (1.0f + erff(ee * 0.70710678118654752f));
        wj = expf(-ge);
    }

    float4 acc = make_float4(0.f, 0.f, 0.f, 0.f);
    float wsum = 0.0f;
#pragma unroll
    for (int j = 0; j < DEG; j++) {
        float w = __shfl_sync(0xffffffffu, wj, j);
        int   d = __shfl_sync(0xffffffffu, dj, j);
        float4 m = *(const float4*)&g_mxT[(size_t)d * 128 + lane * 4];
        acc.x += w * m.x; acc.y += w * m.y; acc.z += w * m.z; acc.w += w * m.w;
        wsum += w;
    }
    float4 al  = *(const float4*)&g_alpha[lane * 4];
    float  inv = 1.0f / wsum;
    float4 hp = make_float4(acc.x * al.x * inv, acc.y * al.y * inv,
                            acc.z * al.z * inv, acc.w * al.w * inv);
    float4 e4;
    e4.x = (hp.x > 0.f) ? hp.x : expm1f(hp.x);
    e4.y = (hp.y > 0.f) ? hp.y : expm1f(hp.y);
    e4.z = (hp.z > 0.f) ? hp.z : expm1f(hp.z);
    e4.w = (hp.w > 0.f) ? hp.w : expm1f(hp.w);
    float ssq = e4.x * e4.x + e4.y * e4.y + e4.z * e4.z + e4.w * e4.w;
#pragma unroll
    for (int o = 16; o > 0; o >>= 1) ssq += __shfl_xor_sync(0xffffffffu, ssq, o);
    float un  = fmaxf(sqrtf(ssq), MIN_NORM);
    float fac = expmap0_proj_factor(un);
    float4 o4 = make_float4(e4.x * fac, e4.y * fac, e4.z * fac, e4.w * fac);
    *(float4*)&out[(size_t)n * 128 + lane * 4] = o4;
}

// ---------------- launch --------------------------------------------------------
extern "C" void kernel_launch(void* const* d_in, const int* in_sizes, int n_in,
                              void* d_out, int out_size) {
    const float* x = nullptr;
    const float* W = nullptr;
    const float* a = nullptr;
    const int* edge = nullptr;
    for (int i = 0; i < n_in; i++) {
        switch (in_sizes[i]) {
            case N_NODES * F_DIM: x    = (const float*)d_in[i]; break;
            case 2 * N_EDGES:     edge = (const int*)d_in[i];   break;
            case F_DIM * F_DIM:   W    = (const float*)d_in[i]; break;
            case 2 * F_DIM:       a    = (const float*)d_in[i]; break;
            default: break;
        }
    }
    const int* src = edge;
    const int* dst = edge + N_EDGES;
    float* out = (float*)d_out;

    cudaFuncSetAttribute(k_gemm_mma, cudaFuncAttributeMaxDynamicSharedMemorySize, SM_TOT);

    k_zw<<<(N_NODES + 255) / 256, 256>>>(W);
    k_hist<<<(N_EDGES + 255) / 256, 256>>>(dst);
    k_gemm_mma<<<(N_NODES + 127) / 128, 256, SM_TOT>>>(x, W);
    k_scalars<<<1, 256>>>(a);
    {
        long long thr = (long long)N_NODES * 32;
        k_uv<<<(unsigned)((thr + 255) / 256), 256>>>();
    }
    k_sumsq<<<(N_EDGES + 255) / 256, 256>>>(src, dst);
    {
        long long thr = (long long)N_NODES * 32;
        k_final<<<(unsigned)((thr + 255) / 256), 256>>>(src, dst, out);
    }
    (void)out_size;
}